// round 7
// baseline (speedup 1.0000x reference)
#include <cuda_runtime.h>
#include <math.h>
#include <stdint.h>

#define N_LEVELS   16
#define HASH_SIZE  (1u << 19)
#define HASH_MASK  (HASH_SIZE - 1u)
#define BLOCK      256
#define MAXN       (1 << 20)

// Morton binning: 5 bits/dim -> 2^15 buckets (avg 32 points/bucket at N=1M).
#define BPD        5
#define NB         (1 << (3 * BPD))

__device__ unsigned g_cnt[NB];    // zero-init at module load; scan re-zeroes it
__device__ unsigned g_off[NB];
__device__ float4   g_pk[MAXN];   // (x, y, z, bitcast(original index)), permuted

struct Res16 { float r[N_LEVELS]; };

// ---------------------------------------------------------------------------

__device__ __forceinline__ unsigned morton_bucket(float px, float py, float pz) {
    unsigned cx = (unsigned)(px * 32.0f); cx = cx > 31u ? 31u : cx;
    unsigned cy = (unsigned)(py * 32.0f); cy = cy > 31u ? 31u : cy;
    unsigned cz = (unsigned)(pz * 32.0f); cz = cz > 31u ? 31u : cz;
    unsigned key = 0;
    #pragma unroll
    for (int b = 0; b < BPD; ++b) {
        key |= ((cx >> b) & 1u) << (3 * b)
             | ((cy >> b) & 1u) << (3 * b + 1)
             | ((cz >> b) & 1u) << (3 * b + 2);
    }
    return key;
}

__global__ void hist_kernel(const float* __restrict__ xin, int n) {
    int j = blockIdx.x * blockDim.x + threadIdx.x;
    if (j >= n) return;
    unsigned b = morton_bucket(xin[3 * j], xin[3 * j + 1], xin[3 * j + 2]);
    atomicAdd(&g_cnt[b], 1u);
}

// Single-block vectorized exclusive scan of g_cnt -> g_off.
// Also re-zeroes g_cnt so the next kernel_launch starts from zeros
// (g_cnt is zero at module load; this keeps the invariant every call).
__global__ __launch_bounds__(1024) void scan_kernel() {
    __shared__ unsigned s[1024];
    const int t = threadIdx.x;
    uint4* c4 = reinterpret_cast<uint4*>(g_cnt);
    uint4* o4 = reinterpret_cast<uint4*>(g_off);

    uint4 v[8];
    unsigned sum = 0;
    #pragma unroll
    for (int k = 0; k < 8; ++k) {
        v[k] = c4[t * 8 + k];
        sum += v[k].x + v[k].y + v[k].z + v[k].w;
    }
    const uint4 z4 = make_uint4(0u, 0u, 0u, 0u);
    #pragma unroll
    for (int k = 0; k < 8; ++k) c4[t * 8 + k] = z4;

    s[t] = sum;
    __syncthreads();

    for (int off = 1; off < 1024; off <<= 1) {
        unsigned u = (t >= off) ? s[t - off] : 0u;
        __syncthreads();
        s[t] += u;
        __syncthreads();
    }

    unsigned run = s[t] - sum;
    #pragma unroll
    for (int k = 0; k < 8; ++k) {
        uint4 o;
        o.x = run; run += v[k].x;
        o.y = run; run += v[k].y;
        o.z = run; run += v[k].z;
        o.w = run; run += v[k].w;
        o4[t * 8 + k] = o;
    }
}

__global__ void scatter_kernel(const float* __restrict__ xin, int n) {
    int j = blockIdx.x * blockDim.x + threadIdx.x;
    if (j >= n) return;
    const float px = xin[3 * j + 0];
    const float py = xin[3 * j + 1];
    const float pz = xin[3 * j + 2];
    unsigned b = morton_bucket(px, py, pz);
    unsigned p = atomicAdd(&g_off[b], 1u);
    float4 v;
    v.x = px; v.y = py; v.z = pz; v.w = __uint_as_float((unsigned)j);
    g_pk[p] = v;   // single STG.128
}

// ---------------------------------------------------------------------------

__device__ __forceinline__ float2 lerp2(float2 a, float2 b, float t) {
    float2 o;
    o.x = fmaf(t, b.x - a.x, a.x);
    o.y = fmaf(t, b.y - a.y, a.y);
    return o;
}

__global__ __launch_bounds__(BLOCK) void hash_encode_kernel(
    const float* __restrict__ tables,
    float* __restrict__ out,
    Res16 rp, int n)
{
    __shared__ float    s_acc[BLOCK * 33];   // staged output rows (pad 33)
    __shared__ unsigned sperm[BLOCK];

    const int base = blockIdx.x * BLOCK;
    const int t = threadIdx.x;
    const int nblk = min(BLOCK, n - base);
    const int j = base + t;

    if (t < nblk) {
        const float4 pk = g_pk[j];           // coalesced LDG.128
        const float px = pk.x, py = pk.y, pz = pk.z;
        sperm[t] = __float_as_uint(pk.w);

        float acc[2 * N_LEVELS];

        #pragma unroll
        for (int L = 0; L < N_LEVELS; ++L) {
            const float res = rp.r[L];
            const float sx = px * res;
            const float sy = py * res;
            const float sz = pz * res;
            const int ix = (int)sx;          // trunc == floor for x >= 0
            const int iy = (int)sy;
            const int iz = (int)sz;
            const float fx = sx - (float)ix;
            const float fy = sy - (float)iy;
            const float fz = sz - (float)iz;

            const unsigned ux0 = (unsigned)ix;
            const unsigned hy0 = (unsigned)iy * 2654435761u;
            const unsigned hy1 = hy0 + 2654435761u;
            const unsigned hz0 = (unsigned)iz * 805459861u;
            const unsigned hz1 = hz0 + 805459861u;

            const unsigned c00 = ux0 ^ hy0;   // x0,y0
            const unsigned c01 = ux0 ^ hy1;   // x0,y1

            const unsigned i000 = (c00 ^ hz0) & HASH_MASK;
            const unsigned i010 = (c01 ^ hz0) & HASH_MASK;
            const unsigned i001 = (c00 ^ hz1) & HASH_MASK;
            const unsigned i011 = (c01 ^ hz1) & HASH_MASK;

            const float2* __restrict__ tab2 =
                reinterpret_cast<const float2*>(tables) + (size_t)L * HASH_SIZE;
            const float4* __restrict__ tab4 =
                reinterpret_cast<const float4*>(tab2);

            // PI_x == 1: entries {idx, idx^1} form one aligned float4.
            // When ix is even, the x+1 corner is idx^1 -> same float4.
            const float4 F000 = __ldg(tab4 + (i000 >> 1));
            const float4 F010 = __ldg(tab4 + (i010 >> 1));
            const float4 F001 = __ldg(tab4 + (i001 >> 1));
            const float4 F011 = __ldg(tab4 + (i011 >> 1));

            float2 g000, g010, g001, g011;   // x+1 corners
            if (ux0 & 1u) {
                // odd ix: x+1 hash not XOR-related; 4 extra gathers
                // (only ~half the lanes active -> half the wavefronts)
                const unsigned ux1 = ux0 + 1u;
                const unsigned d00 = ux1 ^ hy0;
                const unsigned d01 = ux1 ^ hy1;
                g000 = __ldg(tab2 + ((d00 ^ hz0) & HASH_MASK));
                g010 = __ldg(tab2 + ((d01 ^ hz0) & HASH_MASK));
                g001 = __ldg(tab2 + ((d00 ^ hz1) & HASH_MASK));
                g011 = __ldg(tab2 + ((d01 ^ hz1) & HASH_MASK));
            } else {
                // even ix: x+1 corner is the other half of the float4
                g000 = (i000 & 1u) ? make_float2(F000.x, F000.y) : make_float2(F000.z, F000.w);
                g010 = (i010 & 1u) ? make_float2(F010.x, F010.y) : make_float2(F010.z, F010.w);
                g001 = (i001 & 1u) ? make_float2(F001.x, F001.y) : make_float2(F001.z, F001.w);
                g011 = (i011 & 1u) ? make_float2(F011.x, F011.y) : make_float2(F011.z, F011.w);
            }

            // x0 corners: select the half addressed by the low index bit
            const float2 f000 = (i000 & 1u) ? make_float2(F000.z, F000.w) : make_float2(F000.x, F000.y);
            const float2 f010 = (i010 & 1u) ? make_float2(F010.z, F010.w) : make_float2(F010.x, F010.y);
            const float2 f001 = (i001 & 1u) ? make_float2(F001.z, F001.w) : make_float2(F001.x, F001.y);
            const float2 f011 = (i011 & 1u) ? make_float2(F011.z, F011.w) : make_float2(F011.x, F011.y);

            // trilinear lerp tree (x, then y, then z) — same math as before
            const float2 v00 = lerp2(f000, g000, fx);
            const float2 v10 = lerp2(f010, g010, fx);
            const float2 v01 = lerp2(f001, g001, fx);
            const float2 v11 = lerp2(f011, g011, fx);
            const float2 w0  = lerp2(v00, v10, fy);
            const float2 w1  = lerp2(v01, v11, fy);
            const float2 rr  = lerp2(w0, w1, fz);

            acc[2 * L + 0] = rr.x;
            acc[2 * L + 1] = rr.y;
        }

        float* myrow = &s_acc[t * 33];
        #pragma unroll
        for (int k = 0; k < 2 * N_LEVELS; ++k) myrow[k] = acc[k];
    }
    __syncthreads();

    // transpose store: each row (point) is exactly one 128B line in out.
    const int wid  = t >> 5;
    const int lane = t & 31;
    const int rend = min((wid + 1) * 32, nblk);
    for (int r = wid * 32; r < rend; ++r) {
        const size_t i = (size_t)sperm[r];
        out[i * (2 * N_LEVELS) + lane] = s_acc[r * 33 + lane];
    }
}

// ---------------------------------------------------------------------------

extern "C" void kernel_launch(void* const* d_in, const int* in_sizes, int n_in,
                              void* d_out, int out_size) {
    const float* x      = (const float*)d_in[0];
    const float* tables = (const float*)d_in[1];
    float* out          = (float*)d_out;

    const int n = in_sizes[0] / 3;

    // Resolutions exactly as the reference computes them.
    Res16 rp;
    const double growth = pow(512.0 / 16.0, 1.0 / (double)(N_LEVELS - 1));
    for (int l = 0; l < N_LEVELS; ++l) {
        double r = 16.0 * pow(growth, (double)l);
        rp.r[l] = (float)(long long)r;
    }

    const int blocks = (n + BLOCK - 1) / BLOCK;

    hist_kernel<<<blocks, BLOCK>>>(x, n);
    scan_kernel<<<1, 1024>>>();          // also re-zeroes g_cnt
    scatter_kernel<<<blocks, BLOCK>>>(x, n);
    hash_encode_kernel<<<blocks, BLOCK>>>(tables, out, rp, n);
}